// round 5
// baseline (speedup 1.0000x reference)
#include <cuda_runtime.h>
#include <cuda_bf16.h>
#include <cstdint>

#define N_NODES 100000
#define N_EDGES 3200000
#define IN_DIM  128
#define HID     32
#define OUT     12
#define SCAN_B  1024
#define N_SCANB ((N_NODES + SCAN_B - 1) / SCAN_B)   // 98

// ---------------- scratch (allocation-free: __device__ globals) ----------------
__device__ float g_h1 [N_NODES * HID];   // feat @ W1
__device__ float g_x1 [N_NODES * HID];   // relu(norm(agg1)+b1)
__device__ float g_h2 [N_NODES * OUT];   // x1 @ W2
__device__ int   g_cnt[N_NODES];         // in-degree (counts)
__device__ int   g_off[N_NODES];         // exclusive scan of counts
__device__ int   g_cur[N_NODES];         // binning cursors
__device__ int   g_bin[N_EDGES];         // src ids grouped by dst
__device__ int   g_part[128];            // scan block partials

// ---------------- GEMM 1: h1[N,32] = feat[N,128] @ W1[128,32] ----------------
__global__ void gemm1_kernel(const float* __restrict__ feat,
                             const float* __restrict__ W1,
                             float* __restrict__ h1) {
    __shared__ float sW[IN_DIM * HID];
    int tid = threadIdx.x;
    for (int i = tid; i < IN_DIM * HID; i += 256) sW[i] = W1[i];
    __syncthreads();
    int node = blockIdx.x * 32 + (tid >> 3);
    if (node >= N_NODES) return;
    int jj = (tid & 7) * 4;
    const float4* frow = reinterpret_cast<const float4*>(feat + (size_t)node * IN_DIM);
    float4 acc = make_float4(0.f, 0.f, 0.f, 0.f);
    #pragma unroll
    for (int k4 = 0; k4 < IN_DIM / 4; k4++) {
        float4 f = frow[k4];
        #pragma unroll
        for (int u = 0; u < 4; u++) {
            float fk = (u == 0) ? f.x : (u == 1) ? f.y : (u == 2) ? f.z : f.w;
            float4 w = *reinterpret_cast<const float4*>(&sW[(k4 * 4 + u) * HID + jj]);
            acc.x = fmaf(fk, w.x, acc.x);
            acc.y = fmaf(fk, w.y, acc.y);
            acc.z = fmaf(fk, w.z, acc.z);
            acc.w = fmaf(fk, w.w, acc.w);
        }
    }
    *reinterpret_cast<float4*>(h1 + (size_t)node * HID + jj) = acc;
}

// ---------------- CSR build: count -> scan -> bin ----------------
__global__ void count_kernel(const int* __restrict__ dst, int* __restrict__ cnt) {
    int e = blockIdx.x * blockDim.x + threadIdx.x;
    if (e < N_EDGES) atomicAdd(cnt + dst[e], 1);
}

__global__ void scanA_kernel(const int* __restrict__ cnt,
                             int* __restrict__ off, int* __restrict__ part) {
    __shared__ int wsum[32];
    int i = blockIdx.x * SCAN_B + threadIdx.x;
    int lane = threadIdx.x & 31, w = threadIdx.x >> 5;
    int v = (i < N_NODES) ? cnt[i] : 0;
    int x = v;
    #pragma unroll
    for (int d = 1; d < 32; d <<= 1) {
        int y = __shfl_up_sync(~0u, x, d);
        if (lane >= d) x += y;
    }
    if (lane == 31) wsum[w] = x;
    __syncthreads();
    if (w == 0) {
        int s = wsum[lane];
        #pragma unroll
        for (int d = 1; d < 32; d <<= 1) {
            int y = __shfl_up_sync(~0u, s, d);
            if (lane >= d) s += y;
        }
        wsum[lane] = s;
    }
    __syncthreads();
    int base = (w > 0) ? wsum[w - 1] : 0;
    if (i < N_NODES) off[i] = base + x - v;     // local exclusive
    if (threadIdx.x == SCAN_B - 1) part[blockIdx.x] = base + x;  // block total
}

__global__ void scanB_kernel(int* __restrict__ part) {   // n = N_SCANB <= 128
    __shared__ int ws[4];
    int lane = threadIdx.x & 31, w = threadIdx.x >> 5;
    int v = (threadIdx.x < N_SCANB) ? part[threadIdx.x] : 0;
    int x = v;
    #pragma unroll
    for (int d = 1; d < 32; d <<= 1) {
        int y = __shfl_up_sync(~0u, x, d);
        if (lane >= d) x += y;
    }
    if (lane == 31) ws[w] = x;
    __syncthreads();
    int base = 0;
    for (int k = 0; k < w; k++) base += ws[k];
    if (threadIdx.x < N_SCANB) part[threadIdx.x] = base + x - v;  // exclusive
}

__global__ void scanC_kernel(int* __restrict__ off, const int* __restrict__ part,
                             int* __restrict__ cur) {
    int i = blockIdx.x * SCAN_B + threadIdx.x;
    if (i >= N_NODES) return;
    int o = off[i] + part[blockIdx.x];
    off[i] = o;
    cur[i] = o;
}

__global__ void bin_kernel(const int* __restrict__ src, const int* __restrict__ dst,
                           int* __restrict__ cur, int* __restrict__ bin) {
    int e = blockIdx.x * blockDim.x + threadIdx.x;
    if (e >= N_EDGES) return;
    int pos = atomicAdd(cur + dst[e], 1);
    bin[pos] = src[e];
}

// ---------------- agg1 (fused finalize1): x1 = relu(sum(h1[srcs])/deg + b1) ----------------
// one warp per node: 4 edge-slots x 8 chunk-lanes
__global__ void agg1_kernel(const float* __restrict__ h1,
                            const int* __restrict__ bin,
                            const int* __restrict__ off,
                            const int* __restrict__ cnt,
                            const float* __restrict__ b1,
                            float* __restrict__ x1) {
    int gw = (blockIdx.x * 256 + threadIdx.x) >> 5;   // node
    if (gw >= N_NODES) return;
    int lane = threadIdx.x & 31;
    int eg = lane >> 3;       // 0..3 edge slot
    int c  = lane & 7;        // chunk (float4 index)
    int start = off[gw], n = cnt[gw];
    float4 acc = make_float4(0.f, 0.f, 0.f, 0.f);
    for (int i = eg; i < n; i += 4) {
        int s = __ldg(bin + start + i);                     // broadcast across 8 lanes
        float4 v = *reinterpret_cast<const float4*>(h1 + (size_t)s * HID + c * 4);
        acc.x += v.x; acc.y += v.y; acc.z += v.z; acc.w += v.w;
    }
    #pragma unroll
    for (int d = 8; d < 32; d <<= 1) {
        acc.x += __shfl_xor_sync(~0u, acc.x, d);
        acc.y += __shfl_xor_sync(~0u, acc.y, d);
        acc.z += __shfl_xor_sync(~0u, acc.z, d);
        acc.w += __shfl_xor_sync(~0u, acc.w, d);
    }
    if (eg == 0) {
        float inv = 1.0f / fmaxf((float)n, 1.0f);
        float4 bb = *reinterpret_cast<const float4*>(b1 + c * 4);
        float4 r;
        r.x = fmaxf(fmaf(acc.x, inv, bb.x), 0.f);
        r.y = fmaxf(fmaf(acc.y, inv, bb.y), 0.f);
        r.z = fmaxf(fmaf(acc.z, inv, bb.z), 0.f);
        r.w = fmaxf(fmaf(acc.w, inv, bb.w), 0.f);
        *reinterpret_cast<float4*>(x1 + (size_t)gw * HID + c * 4) = r;
    }
}

// ---------------- GEMM 2: h2[N,12] = x1[N,32] @ W2[32,12] ----------------
__global__ void gemm2_kernel(const float* __restrict__ x1,
                             const float* __restrict__ W2,
                             float* __restrict__ h2) {
    __shared__ float sW[HID * OUT];
    __shared__ float sx[8][HID];
    int tid = threadIdx.x;
    for (int i = tid; i < HID * OUT; i += 256) sW[i] = W2[i];
    __syncthreads();
    int w = tid >> 5, lane = tid & 31;
    int node = blockIdx.x * 8 + w;
    if (node >= N_NODES) return;
    sx[w][lane] = x1[(size_t)node * HID + lane];
    __syncwarp();
    if (lane < OUT) {
        float acc = 0.f;
        #pragma unroll
        for (int k = 0; k < HID; k++)
            acc = fmaf(sx[w][k], sW[k * OUT + lane], acc);
        h2[(size_t)node * OUT + lane] = acc;
    }
}

// ---------------- agg2 (fused finalize2): out = relu(sum(h2[srcs])/deg + b2) ----------------
// one warp per node: each lane owns whole edges (3 float4 per edge)
__global__ void agg2_kernel(const float* __restrict__ h2,
                            const int* __restrict__ bin,
                            const int* __restrict__ off,
                            const int* __restrict__ cnt,
                            const float* __restrict__ b2,
                            float* __restrict__ out) {
    int gw = (blockIdx.x * 256 + threadIdx.x) >> 5;   // node
    if (gw >= N_NODES) return;
    int lane = threadIdx.x & 31;
    int start = off[gw], n = cnt[gw];
    float4 a0 = make_float4(0, 0, 0, 0), a1 = a0, a2 = a0;
    for (int i = lane; i < n; i += 32) {
        int s = __ldg(bin + start + i);
        const float4* r = reinterpret_cast<const float4*>(h2 + (size_t)s * OUT);
        float4 v0 = r[0], v1 = r[1], v2 = r[2];
        a0.x += v0.x; a0.y += v0.y; a0.z += v0.z; a0.w += v0.w;
        a1.x += v1.x; a1.y += v1.y; a1.z += v1.z; a1.w += v1.w;
        a2.x += v2.x; a2.y += v2.y; a2.z += v2.z; a2.w += v2.w;
    }
    #pragma unroll
    for (int d = 16; d >= 1; d >>= 1) {
        a0.x += __shfl_xor_sync(~0u, a0.x, d);
        a0.y += __shfl_xor_sync(~0u, a0.y, d);
        a0.z += __shfl_xor_sync(~0u, a0.z, d);
        a0.w += __shfl_xor_sync(~0u, a0.w, d);
        a1.x += __shfl_xor_sync(~0u, a1.x, d);
        a1.y += __shfl_xor_sync(~0u, a1.y, d);
        a1.z += __shfl_xor_sync(~0u, a1.z, d);
        a1.w += __shfl_xor_sync(~0u, a1.w, d);
        a2.x += __shfl_xor_sync(~0u, a2.x, d);
        a2.y += __shfl_xor_sync(~0u, a2.y, d);
        a2.z += __shfl_xor_sync(~0u, a2.z, d);
        a2.w += __shfl_xor_sync(~0u, a2.w, d);
    }
    if (lane == 0) {
        float inv = 1.0f / fmaxf((float)n, 1.0f);
        float4* o = reinterpret_cast<float4*>(out + (size_t)gw * OUT);
        const float4* bb = reinterpret_cast<const float4*>(b2);
        float4 b0 = bb[0], bq1 = bb[1], bq2 = bb[2];
        float4 r0, r1, r2;
        r0.x = fmaxf(fmaf(a0.x, inv, b0.x), 0.f);
        r0.y = fmaxf(fmaf(a0.y, inv, b0.y), 0.f);
        r0.z = fmaxf(fmaf(a0.z, inv, b0.z), 0.f);
        r0.w = fmaxf(fmaf(a0.w, inv, b0.w), 0.f);
        r1.x = fmaxf(fmaf(a1.x, inv, bq1.x), 0.f);
        r1.y = fmaxf(fmaf(a1.y, inv, bq1.y), 0.f);
        r1.z = fmaxf(fmaf(a1.z, inv, bq1.z), 0.f);
        r1.w = fmaxf(fmaf(a1.w, inv, bq1.w), 0.f);
        r2.x = fmaxf(fmaf(a2.x, inv, bq2.x), 0.f);
        r2.y = fmaxf(fmaf(a2.y, inv, bq2.y), 0.f);
        r2.z = fmaxf(fmaf(a2.z, inv, bq2.z), 0.f);
        r2.w = fmaxf(fmaf(a2.w, inv, bq2.w), 0.f);
        o[0] = r0; o[1] = r1; o[2] = r2;
    }
}

// ---------------- launch ----------------
extern "C" void kernel_launch(void* const* d_in, const int* in_sizes, int n_in,
                              void* d_out, int out_size) {
    const float* feat = (const float*)d_in[0];
    const int*   src  = (const int*)  d_in[1];
    const int*   dst  = (const int*)  d_in[2];
    const float* W1   = (const float*)d_in[3];
    const float* b1   = (const float*)d_in[4];
    const float* W2   = (const float*)d_in[5];
    const float* b2   = (const float*)d_in[6];
    float* out = (float*)d_out;

    void *p_h1, *p_x1, *p_h2, *p_cnt, *p_off, *p_cur, *p_bin, *p_part;
    cudaGetSymbolAddress(&p_h1, g_h1);
    cudaGetSymbolAddress(&p_x1, g_x1);
    cudaGetSymbolAddress(&p_h2, g_h2);
    cudaGetSymbolAddress(&p_cnt, g_cnt);
    cudaGetSymbolAddress(&p_off, g_off);
    cudaGetSymbolAddress(&p_cur, g_cur);
    cudaGetSymbolAddress(&p_bin, g_bin);
    cudaGetSymbolAddress(&p_part, g_part);
    float* h1 = (float*)p_h1;
    float* x1 = (float*)p_x1;
    float* h2 = (float*)p_h2;
    int* cnt = (int*)p_cnt;
    int* off = (int*)p_off;
    int* cur = (int*)p_cur;
    int* bin = (int*)p_bin;
    int* part = (int*)p_part;

    cudaMemsetAsync(p_cnt, 0, sizeof(int) * N_NODES, 0);

    // CSR build
    count_kernel<<<(N_EDGES + 255) / 256, 256>>>(dst, cnt);
    scanA_kernel<<<N_SCANB, SCAN_B>>>(cnt, off, part);
    scanB_kernel<<<1, 128>>>(part);
    scanC_kernel<<<N_SCANB, SCAN_B>>>(off, part, cur);
    bin_kernel<<<(N_EDGES + 255) / 256, 256>>>(src, dst, cur, bin);

    // layer 1
    gemm1_kernel<<<(N_NODES + 31) / 32, 256>>>(feat, W1, h1);
    agg1_kernel<<<(N_NODES * 32 + 255) / 256, 256>>>(h1, bin, off, cnt, b1, x1);

    // layer 2
    gemm2_kernel<<<(N_NODES + 7) / 8, 256>>>(x1, W2, h2);
    agg2_kernel<<<(N_NODES * 32 + 255) / 256, 256>>>(h2, bin, off, cnt, b2, out);
}

// round 6
// speedup vs baseline: 1.1575x; 1.1575x over previous
#include <cuda_runtime.h>
#include <cuda_bf16.h>
#include <cstdint>

#define N_NODES 100000
#define N_EDGES 3200000
#define IN_DIM  128
#define HID     32
#define OUT     12
#define H2P     16                                   // padded h2 row (floats)
#define SCAN_B  1024
#define N_SCANB ((N_NODES + SCAN_B - 1) / SCAN_B)    // 98
#define GEMM1_BLOCKS ((N_NODES + 31) / 32)           // 3125
#define COUNT_BLOCKS ((N_EDGES + 255) / 256)         // 12500

// ---------------- scratch (allocation-free: __device__ globals) ----------------
__device__ float g_h1 [N_NODES * HID];   // feat @ W1
__device__ float g_h2 [N_NODES * H2P];   // relu(norm(agg1)+b1) @ W2, padded rows
__device__ int   g_cnt[N_NODES];         // in-degree
__device__ int   g_off[N_NODES];         // exclusive scan of counts
__device__ int   g_cur[N_NODES];         // binning cursors
__device__ int   g_bin[N_EDGES];         // src ids grouped by dst
__device__ int   g_part[128];            // scan block partials

// ---------------- fused: gemm1 (blocks [0,GEMM1_BLOCKS)) + degree count ----------------
__global__ void fusedA_kernel(const float* __restrict__ feat,
                              const float* __restrict__ W1,
                              float* __restrict__ h1,
                              const int* __restrict__ dst,
                              int* __restrict__ cnt) {
    __shared__ float sW[IN_DIM * HID];               // 16 KB (gemm branch only)
    int tid = threadIdx.x;
    if (blockIdx.x < GEMM1_BLOCKS) {
        for (int i = tid; i < IN_DIM * HID; i += 256) sW[i] = W1[i];
        __syncthreads();
        int node = blockIdx.x * 32 + (tid >> 3);
        if (node >= N_NODES) return;
        int jj = (tid & 7) * 4;
        const float4* frow = reinterpret_cast<const float4*>(feat + (size_t)node * IN_DIM);
        float4 acc = make_float4(0.f, 0.f, 0.f, 0.f);
        #pragma unroll
        for (int k4 = 0; k4 < IN_DIM / 4; k4++) {
            float4 f = frow[k4];
            #pragma unroll
            for (int u = 0; u < 4; u++) {
                float fk = (u == 0) ? f.x : (u == 1) ? f.y : (u == 2) ? f.z : f.w;
                float4 w = *reinterpret_cast<const float4*>(&sW[(k4 * 4 + u) * HID + jj]);
                acc.x = fmaf(fk, w.x, acc.x);
                acc.y = fmaf(fk, w.y, acc.y);
                acc.z = fmaf(fk, w.z, acc.z);
                acc.w = fmaf(fk, w.w, acc.w);
            }
        }
        *reinterpret_cast<float4*>(h1 + (size_t)node * HID + jj) = acc;
    } else {
        int e = (blockIdx.x - GEMM1_BLOCKS) * 256 + tid;
        if (e < N_EDGES) atomicAdd(cnt + dst[e], 1);
    }
}

// ---------------- scan (3 phases) ----------------
__global__ void scanA_kernel(const int* __restrict__ cnt,
                             int* __restrict__ off, int* __restrict__ part) {
    __shared__ int wsum[32];
    int i = blockIdx.x * SCAN_B + threadIdx.x;
    int lane = threadIdx.x & 31, w = threadIdx.x >> 5;
    int v = (i < N_NODES) ? cnt[i] : 0;
    int x = v;
    #pragma unroll
    for (int d = 1; d < 32; d <<= 1) {
        int y = __shfl_up_sync(~0u, x, d);
        if (lane >= d) x += y;
    }
    if (lane == 31) wsum[w] = x;
    __syncthreads();
    if (w == 0) {
        int s = wsum[lane];
        #pragma unroll
        for (int d = 1; d < 32; d <<= 1) {
            int y = __shfl_up_sync(~0u, s, d);
            if (lane >= d) s += y;
        }
        wsum[lane] = s;
    }
    __syncthreads();
    int base = (w > 0) ? wsum[w - 1] : 0;
    if (i < N_NODES) off[i] = base + x - v;
    if (threadIdx.x == SCAN_B - 1) part[blockIdx.x] = base + x;
}

__global__ void scanB_kernel(int* __restrict__ part) {   // N_SCANB <= 128
    __shared__ int ws[4];
    int lane = threadIdx.x & 31, w = threadIdx.x >> 5;
    int v = (threadIdx.x < N_SCANB) ? part[threadIdx.x] : 0;
    int x = v;
    #pragma unroll
    for (int d = 1; d < 32; d <<= 1) {
        int y = __shfl_up_sync(~0u, x, d);
        if (lane >= d) x += y;
    }
    if (lane == 31) ws[w] = x;
    __syncthreads();
    int base = 0;
    for (int k = 0; k < w; k++) base += ws[k];
    if (threadIdx.x < N_SCANB) part[threadIdx.x] = base + x - v;
}

__global__ void scanC_kernel(int* __restrict__ off, const int* __restrict__ part,
                             int* __restrict__ cur) {
    int i = blockIdx.x * SCAN_B + threadIdx.x;
    if (i >= N_NODES) return;
    int o = off[i] + part[blockIdx.x];
    off[i] = o;
    cur[i] = o;
}

__global__ void bin_kernel(const int* __restrict__ src, const int* __restrict__ dst,
                           int* __restrict__ cur, int* __restrict__ bin) {
    int e = blockIdx.x * blockDim.x + threadIdx.x;
    if (e >= N_EDGES) return;
    int pos = atomicAdd(cur + dst[e], 1);
    bin[pos] = src[e];
}

// ---------------- agg1 + finalize1 + gemm2 fused ----------------
// one warp per node: 4 edge-slots x 8 chunk-lanes gather/reduce h1 rows,
// x1 row staged in smem, 12 lanes compute h2 = x1 @ W2.
__global__ void agg1g2_kernel(const float* __restrict__ h1,
                              const int* __restrict__ bin,
                              const int* __restrict__ off,
                              const int* __restrict__ cnt,
                              const float* __restrict__ b1,
                              const float* __restrict__ W2,
                              float* __restrict__ h2) {
    __shared__ float sW[HID * OUT];     // 1.5 KB
    __shared__ float sx[8][HID];
    int tid = threadIdx.x;
    for (int i = tid; i < HID * OUT; i += 256) sW[i] = W2[i];
    __syncthreads();
    int w = tid >> 5, lane = tid & 31;
    int node = blockIdx.x * 8 + w;
    if (node >= N_NODES) return;
    int eg = lane >> 3;       // 0..3 edge slot
    int c  = lane & 7;        // chunk (float4 index)
    int start = off[node], n = cnt[node];
    float4 acc = make_float4(0.f, 0.f, 0.f, 0.f);
    for (int i = eg; i < n; i += 4) {
        int s = __ldg(bin + start + i);
        float4 v = *reinterpret_cast<const float4*>(h1 + (size_t)s * HID + c * 4);
        acc.x += v.x; acc.y += v.y; acc.z += v.z; acc.w += v.w;
    }
    #pragma unroll
    for (int d = 8; d < 32; d <<= 1) {
        acc.x += __shfl_xor_sync(~0u, acc.x, d);
        acc.y += __shfl_xor_sync(~0u, acc.y, d);
        acc.z += __shfl_xor_sync(~0u, acc.z, d);
        acc.w += __shfl_xor_sync(~0u, acc.w, d);
    }
    if (eg == 0) {
        float inv = 1.0f / fmaxf((float)n, 1.0f);
        float4 bb = *reinterpret_cast<const float4*>(b1 + c * 4);
        sx[w][c * 4 + 0] = fmaxf(fmaf(acc.x, inv, bb.x), 0.f);
        sx[w][c * 4 + 1] = fmaxf(fmaf(acc.y, inv, bb.y), 0.f);
        sx[w][c * 4 + 2] = fmaxf(fmaf(acc.z, inv, bb.z), 0.f);
        sx[w][c * 4 + 3] = fmaxf(fmaf(acc.w, inv, bb.w), 0.f);
    }
    __syncwarp();
    if (lane < OUT) {
        float a = 0.f;
        #pragma unroll
        for (int k = 0; k < HID; k++)
            a = fmaf(sx[w][k], sW[k * OUT + lane], a);
        h2[(size_t)node * H2P + lane] = a;
    }
}

// ---------------- agg2 + finalize2: out = relu(sum(h2[srcs])/deg + b2) ----------------
// one warp per node: 8 edge-slots x 4 chunk-lanes (chunk 3 idle on gather).
__global__ void agg2_kernel(const float* __restrict__ h2,
                            const int* __restrict__ bin,
                            const int* __restrict__ off,
                            const int* __restrict__ cnt,
                            const float* __restrict__ b2,
                            float* __restrict__ out) {
    int gw = (blockIdx.x * 256 + threadIdx.x) >> 5;   // node
    if (gw >= N_NODES) return;
    int lane = threadIdx.x & 31;
    int eg = lane >> 2;       // 0..7 edge slot
    int c  = lane & 3;        // chunk, active c<3
    int start = off[gw], n = cnt[gw];
    float4 acc = make_float4(0.f, 0.f, 0.f, 0.f);
    for (int i = eg; i < n; i += 8) {
        int s = __ldg(bin + start + i);
        if (c < 3) {
            float4 v = *reinterpret_cast<const float4*>(h2 + (size_t)s * H2P + c * 4);
            acc.x += v.x; acc.y += v.y; acc.z += v.z; acc.w += v.w;
        }
    }
    #pragma unroll
    for (int d = 4; d < 32; d <<= 1) {
        acc.x += __shfl_xor_sync(~0u, acc.x, d);
        acc.y += __shfl_xor_sync(~0u, acc.y, d);
        acc.z += __shfl_xor_sync(~0u, acc.z, d);
        acc.w += __shfl_xor_sync(~0u, acc.w, d);
    }
    if (eg == 0 && c < 3) {
        float inv = 1.0f / fmaxf((float)n, 1.0f);
        float4 bb = *reinterpret_cast<const float4*>(b2 + c * 4);
        float4 r;
        r.x = fmaxf(fmaf(acc.x, inv, bb.x), 0.f);
        r.y = fmaxf(fmaf(acc.y, inv, bb.y), 0.f);
        r.z = fmaxf(fmaf(acc.z, inv, bb.z), 0.f);
        r.w = fmaxf(fmaf(acc.w, inv, bb.w), 0.f);
        *reinterpret_cast<float4*>(out + (size_t)gw * OUT + c * 4) = r;
    }
}

// ---------------- launch ----------------
extern "C" void kernel_launch(void* const* d_in, const int* in_sizes, int n_in,
                              void* d_out, int out_size) {
    const float* feat = (const float*)d_in[0];
    const int*   src  = (const int*)  d_in[1];
    const int*   dst  = (const int*)  d_in[2];
    const float* W1   = (const float*)d_in[3];
    const float* b1   = (const float*)d_in[4];
    const float* W2   = (const float*)d_in[5];
    const float* b2   = (const float*)d_in[6];
    float* out = (float*)d_out;

    void *p_h1, *p_h2, *p_cnt, *p_off, *p_cur, *p_bin, *p_part;
    cudaGetSymbolAddress(&p_h1, g_h1);
    cudaGetSymbolAddress(&p_h2, g_h2);
    cudaGetSymbolAddress(&p_cnt, g_cnt);
    cudaGetSymbolAddress(&p_off, g_off);
    cudaGetSymbolAddress(&p_cur, g_cur);
    cudaGetSymbolAddress(&p_bin, g_bin);
    cudaGetSymbolAddress(&p_part, g_part);
    float* h1 = (float*)p_h1;
    float* h2 = (float*)p_h2;
    int* cnt = (int*)p_cnt;
    int* off = (int*)p_off;
    int* cur = (int*)p_cur;
    int* bin = (int*)p_bin;
    int* part = (int*)p_part;

    cudaMemsetAsync(p_cnt, 0, sizeof(int) * N_NODES, 0);

    // gemm1 + degree count in one launch (independent work, partitioned by blockIdx)
    fusedA_kernel<<<GEMM1_BLOCKS + COUNT_BLOCKS, 256>>>(feat, W1, h1, dst, cnt);

    // CSR: scan + bin
    scanA_kernel<<<N_SCANB, SCAN_B>>>(cnt, off, part);
    scanB_kernel<<<1, 128>>>(part);
    scanC_kernel<<<N_SCANB, SCAN_B>>>(off, part, cur);
    bin_kernel<<<COUNT_BLOCKS, 256>>>(src, dst, cur, bin);

    // layer 1 agg + finalize + gemm2 (fused)
    agg1g2_kernel<<<(N_NODES + 7) / 8, 256>>>(h1, bin, off, cnt, b1, W2, h2);

    // layer 2 agg + finalize
    agg2_kernel<<<(N_NODES * 32 + 255) / 256, 256>>>(h2, bin, off, cnt, b2, out);
}

// round 7
// speedup vs baseline: 1.2138x; 1.0487x over previous
#include <cuda_runtime.h>
#include <cuda_fp16.h>
#include <cstdint>

#define N_NODES 100000
#define N_EDGES 3200000
#define IN_DIM  128
#define HID     32
#define OUT     12
#define H2P     16                                   // padded h2 row (halfs)
#define SCAN_B  1024
#define N_SCANB ((N_NODES + SCAN_B - 1) / SCAN_B)    // 98
#define GEMM1_BLOCKS ((N_NODES + 31) / 32)           // 3125
#define EV_BLOCKS    ((N_EDGES / 4 + 255) / 256)     // 3125 (4 edges/thread)

// ---------------- scratch (allocation-free: __device__ globals) ----------------
__device__ __half g_h1 [N_NODES * HID];   // feat @ W1 (fp16)
__device__ __half g_h2 [N_NODES * H2P];   // layer-1 out @ W2 (fp16, padded rows)
__device__ int    g_cnt[N_NODES];
__device__ int    g_off[N_NODES];
__device__ int    g_cur[N_NODES];
__device__ int    g_bin[N_EDGES];
__device__ int    g_part[128];

// ---------------- count: deg via int4 edge reads ----------------
__global__ void count_kernel(const int* __restrict__ dst, int* __restrict__ cnt) {
    int i = blockIdx.x * blockDim.x + threadIdx.x;
    if (i >= N_EDGES / 4) return;
    int4 d4 = reinterpret_cast<const int4*>(dst)[i];
    atomicAdd(cnt + d4.x, 1);
    atomicAdd(cnt + d4.y, 1);
    atomicAdd(cnt + d4.z, 1);
    atomicAdd(cnt + d4.w, 1);
}

// ---------------- scan (3 phases) ----------------
__global__ void scanA_kernel(const int* __restrict__ cnt,
                             int* __restrict__ off, int* __restrict__ part) {
    __shared__ int wsum[32];
    int i = blockIdx.x * SCAN_B + threadIdx.x;
    int lane = threadIdx.x & 31, w = threadIdx.x >> 5;
    int v = (i < N_NODES) ? cnt[i] : 0;
    int x = v;
    #pragma unroll
    for (int d = 1; d < 32; d <<= 1) {
        int y = __shfl_up_sync(~0u, x, d);
        if (lane >= d) x += y;
    }
    if (lane == 31) wsum[w] = x;
    __syncthreads();
    if (w == 0) {
        int s = wsum[lane];
        #pragma unroll
        for (int d = 1; d < 32; d <<= 1) {
            int y = __shfl_up_sync(~0u, s, d);
            if (lane >= d) s += y;
        }
        wsum[lane] = s;
    }
    __syncthreads();
    int base = (w > 0) ? wsum[w - 1] : 0;
    if (i < N_NODES) off[i] = base + x - v;
    if (threadIdx.x == SCAN_B - 1) part[blockIdx.x] = base + x;
}

__global__ void scanB_kernel(int* __restrict__ part) {   // N_SCANB <= 128
    __shared__ int ws[4];
    int lane = threadIdx.x & 31, w = threadIdx.x >> 5;
    int v = (threadIdx.x < N_SCANB) ? part[threadIdx.x] : 0;
    int x = v;
    #pragma unroll
    for (int d = 1; d < 32; d <<= 1) {
        int y = __shfl_up_sync(~0u, x, d);
        if (lane >= d) x += y;
    }
    if (lane == 31) ws[w] = x;
    __syncthreads();
    int base = 0;
    for (int k = 0; k < w; k++) base += ws[k];
    if (threadIdx.x < N_SCANB) part[threadIdx.x] = base + x - v;
}

__global__ void scanC_kernel(int* __restrict__ off, const int* __restrict__ part,
                             int* __restrict__ cur) {
    int i = blockIdx.x * SCAN_B + threadIdx.x;
    if (i >= N_NODES) return;
    int o = off[i] + part[blockIdx.x];
    off[i] = o;
    cur[i] = o;
}

// ---------------- fused: gemm1 (h1 fp16) || bin ----------------
__global__ void fusedB_kernel(const float* __restrict__ feat,
                              const float* __restrict__ W1,
                              __half* __restrict__ h1,
                              const int* __restrict__ src,
                              const int* __restrict__ dst,
                              int* __restrict__ cur,
                              int* __restrict__ bin) {
    __shared__ float sW[IN_DIM * HID];               // 16 KB (gemm branch only)
    int tid = threadIdx.x;
    if (blockIdx.x < GEMM1_BLOCKS) {
        for (int i = tid; i < IN_DIM * HID; i += 256) sW[i] = W1[i];
        __syncthreads();
        int node = blockIdx.x * 32 + (tid >> 3);
        if (node >= N_NODES) return;
        int jj = (tid & 7) * 4;
        const float4* frow = reinterpret_cast<const float4*>(feat + (size_t)node * IN_DIM);
        float4 acc = make_float4(0.f, 0.f, 0.f, 0.f);
        #pragma unroll
        for (int k4 = 0; k4 < IN_DIM / 4; k4++) {
            float4 f = frow[k4];
            #pragma unroll
            for (int u = 0; u < 4; u++) {
                float fk = (u == 0) ? f.x : (u == 1) ? f.y : (u == 2) ? f.z : f.w;
                float4 w = *reinterpret_cast<const float4*>(&sW[(k4 * 4 + u) * HID + jj]);
                acc.x = fmaf(fk, w.x, acc.x);
                acc.y = fmaf(fk, w.y, acc.y);
                acc.z = fmaf(fk, w.z, acc.z);
                acc.w = fmaf(fk, w.w, acc.w);
            }
        }
        half2 p0 = __floats2half2_rn(acc.x, acc.y);
        half2 p1 = __floats2half2_rn(acc.z, acc.w);
        uint2 pk;
        pk.x = *reinterpret_cast<unsigned*>(&p0);
        pk.y = *reinterpret_cast<unsigned*>(&p1);
        *reinterpret_cast<uint2*>(h1 + (size_t)node * HID + jj) = pk;
    } else {
        int i = (blockIdx.x - GEMM1_BLOCKS) * 256 + tid;
        if (i >= N_EDGES / 4) return;
        int4 s4 = reinterpret_cast<const int4*>(src)[i];
        int4 d4 = reinterpret_cast<const int4*>(dst)[i];
        bin[atomicAdd(cur + d4.x, 1)] = s4.x;
        bin[atomicAdd(cur + d4.y, 1)] = s4.y;
        bin[atomicAdd(cur + d4.z, 1)] = s4.z;
        bin[atomicAdd(cur + d4.w, 1)] = s4.w;
    }
}

// ---------------- agg1 + finalize1 + gemm2: one warp per node ----------------
// 8 edge-slots x 4 chunk-lanes; each lane loads 16B = 8 halfs of the 64B row.
__global__ void agg1g2_kernel(const __half* __restrict__ h1,
                              const int* __restrict__ bin,
                              const int* __restrict__ off,
                              const int* __restrict__ cnt,
                              const float* __restrict__ b1,
                              const float* __restrict__ W2,
                              __half* __restrict__ h2) {
    __shared__ float sW[HID * OUT];     // 1.5 KB
    __shared__ float sx[8][HID];
    int tid = threadIdx.x;
    for (int i = tid; i < HID * OUT; i += 256) sW[i] = W2[i];
    __syncthreads();
    int w = tid >> 5, lane = tid & 31;
    int node = blockIdx.x * 8 + w;
    if (node >= N_NODES) return;
    int eg = lane >> 2;       // 0..7 edge slot
    int c  = lane & 3;        // 16B chunk
    int start = off[node], n = cnt[node];
    float4 alo = make_float4(0.f, 0.f, 0.f, 0.f);
    float4 ahi = make_float4(0.f, 0.f, 0.f, 0.f);
    for (int i = eg; i < n; i += 8) {
        int s = __ldg(bin + start + i);
        uint4 v = *reinterpret_cast<const uint4*>(h1 + (size_t)s * HID + c * 8);
        float2 f0 = __half22float2(*reinterpret_cast<half2*>(&v.x));
        float2 f1 = __half22float2(*reinterpret_cast<half2*>(&v.y));
        float2 f2 = __half22float2(*reinterpret_cast<half2*>(&v.z));
        float2 f3 = __half22float2(*reinterpret_cast<half2*>(&v.w));
        alo.x += f0.x; alo.y += f0.y; alo.z += f1.x; alo.w += f1.y;
        ahi.x += f2.x; ahi.y += f2.y; ahi.z += f3.x; ahi.w += f3.y;
    }
    #pragma unroll
    for (int d = 4; d < 32; d <<= 1) {
        alo.x += __shfl_xor_sync(~0u, alo.x, d);
        alo.y += __shfl_xor_sync(~0u, alo.y, d);
        alo.z += __shfl_xor_sync(~0u, alo.z, d);
        alo.w += __shfl_xor_sync(~0u, alo.w, d);
        ahi.x += __shfl_xor_sync(~0u, ahi.x, d);
        ahi.y += __shfl_xor_sync(~0u, ahi.y, d);
        ahi.z += __shfl_xor_sync(~0u, ahi.z, d);
        ahi.w += __shfl_xor_sync(~0u, ahi.w, d);
    }
    if (eg == 0) {
        float inv = 1.0f / fmaxf((float)n, 1.0f);
        float4 bA = *reinterpret_cast<const float4*>(b1 + c * 8);
        float4 bB = *reinterpret_cast<const float4*>(b1 + c * 8 + 4);
        sx[w][c * 8 + 0] = fmaxf(fmaf(alo.x, inv, bA.x), 0.f);
        sx[w][c * 8 + 1] = fmaxf(fmaf(alo.y, inv, bA.y), 0.f);
        sx[w][c * 8 + 2] = fmaxf(fmaf(alo.z, inv, bA.z), 0.f);
        sx[w][c * 8 + 3] = fmaxf(fmaf(alo.w, inv, bA.w), 0.f);
        sx[w][c * 8 + 4] = fmaxf(fmaf(ahi.x, inv, bB.x), 0.f);
        sx[w][c * 8 + 5] = fmaxf(fmaf(ahi.y, inv, bB.y), 0.f);
        sx[w][c * 8 + 6] = fmaxf(fmaf(ahi.z, inv, bB.z), 0.f);
        sx[w][c * 8 + 7] = fmaxf(fmaf(ahi.w, inv, bB.w), 0.f);
    }
    __syncwarp();
    if (lane < OUT) {
        float a = 0.f;
        #pragma unroll
        for (int k = 0; k < HID; k++)
            a = fmaf(sx[w][k], sW[k * OUT + lane], a);
        h2[(size_t)node * H2P + lane] = __float2half(a);
    }
}

// ---------------- agg2 + finalize2: one warp per node ----------------
// 8 edge-slots x 4 chunk-lanes; chunks 0..2 cover the 24B (12-half) row.
__global__ void agg2_kernel(const __half* __restrict__ h2,
                            const int* __restrict__ bin,
                            const int* __restrict__ off,
                            const int* __restrict__ cnt,
                            const float* __restrict__ b2,
                            float* __restrict__ out) {
    int gw = (blockIdx.x * 256 + threadIdx.x) >> 5;   // node
    if (gw >= N_NODES) return;
    int lane = threadIdx.x & 31;
    int eg = lane >> 2;       // 0..7 edge slot
    int c  = lane & 3;        // 8B chunk, active c<3
    int start = off[gw], n = cnt[gw];
    float4 acc = make_float4(0.f, 0.f, 0.f, 0.f);
    for (int i = eg; i < n; i += 8) {
        int s = __ldg(bin + start + i);
        if (c < 3) {
            uint2 v = *reinterpret_cast<const uint2*>(h2 + (size_t)s * H2P + c * 4);
            float2 f0 = __half22float2(*reinterpret_cast<half2*>(&v.x));
            float2 f1 = __half22float2(*reinterpret_cast<half2*>(&v.y));
            acc.x += f0.x; acc.y += f0.y; acc.z += f1.x; acc.w += f1.y;
        }
    }
    #pragma unroll
    for (int d = 4; d < 32; d <<= 1) {
        acc.x += __shfl_xor_sync(~0u, acc.x, d);
        acc.y += __shfl_xor_sync(~0u, acc.y, d);
        acc.z += __shfl_xor_sync(~0u, acc.z, d);
        acc.w += __shfl_xor_sync(~0u, acc.w, d);
    }
    if (eg == 0 && c < 3) {
        float inv = 1.0f / fmaxf((float)n, 1.0f);
        float4 bb = *reinterpret_cast<const float4*>(b2 + c * 4);
        float4 r;
        r.x = fmaxf(fmaf(acc.x, inv, bb.x), 0.f);
        r.y = fmaxf(fmaf(acc.y, inv, bb.y), 0.f);
        r.z = fmaxf(fmaf(acc.z, inv, bb.z), 0.f);
        r.w = fmaxf(fmaf(acc.w, inv, bb.w), 0.f);
        *reinterpret_cast<float4*>(out + (size_t)gw * OUT + c * 4) = r;
    }
}

// ---------------- launch ----------------
extern "C" void kernel_launch(void* const* d_in, const int* in_sizes, int n_in,
                              void* d_out, int out_size) {
    const float* feat = (const float*)d_in[0];
    const int*   src  = (const int*)  d_in[1];
    const int*   dst  = (const int*)  d_in[2];
    const float* W1   = (const float*)d_in[3];
    const float* b1   = (const float*)d_in[4];
    const float* W2   = (const float*)d_in[5];
    const float* b2   = (const float*)d_in[6];
    float* out = (float*)d_out;

    void *p_h1, *p_h2, *p_cnt, *p_off, *p_cur, *p_bin, *p_part;
    cudaGetSymbolAddress(&p_h1, g_h1);
    cudaGetSymbolAddress(&p_h2, g_h2);
    cudaGetSymbolAddress(&p_cnt, g_cnt);
    cudaGetSymbolAddress(&p_off, g_off);
    cudaGetSymbolAddress(&p_cur, g_cur);
    cudaGetSymbolAddress(&p_bin, g_bin);
    cudaGetSymbolAddress(&p_part, g_part);
    __half* h1 = (__half*)p_h1;
    __half* h2 = (__half*)p_h2;
    int* cnt = (int*)p_cnt;
    int* off = (int*)p_off;
    int* cur = (int*)p_cur;
    int* bin = (int*)p_bin;
    int* part = (int*)p_part;

    cudaMemsetAsync(p_cnt, 0, sizeof(int) * N_NODES, 0);

    // CSR: count -> scan
    count_kernel<<<EV_BLOCKS, 256>>>(dst, cnt);
    scanA_kernel<<<N_SCANB, SCAN_B>>>(cnt, off, part);
    scanB_kernel<<<1, 128>>>(part);
    scanC_kernel<<<N_SCANB, SCAN_B>>>(off, part, cur);

    // gemm1 (independent) overlapped with bin (random scatter)
    fusedB_kernel<<<GEMM1_BLOCKS + EV_BLOCKS, 256>>>(feat, W1, h1, src, dst, cur, bin);

    // layer 1 agg + finalize + gemm2
    agg1g2_kernel<<<(N_NODES + 7) / 8, 256>>>(h1, bin, off, cnt, b1, W2, h2);

    // layer 2 agg + finalize
    agg2_kernel<<<(N_NODES * 32 + 255) / 256, 256>>>(h2, bin, off, cnt, b2, out);
}